// round 8
// baseline (speedup 1.0000x reference)
#include <cuda_runtime.h>
#include <cuda_fp16.h>
#include <mma.h>
#include <math.h>

using namespace nvcuda;

#define NPTS 65536
#define CDIM 256
#define KWIN 32
#define NWIN 2048
#define LXYZ 40
#define LRGB 32
#define QSF 4.0f
#define CQSF 8.0f
#define QK_SCALE 0.25f

// value-table layout offsets (halfs), rows transposed [row][c][h][8]
#define T_VX 0
#define T_VR 30720
#define T_VTOT 55296

// combined logit tables per h: [h][224][16] halfs (l<216 valid, rest zero)
#define CT_LSTRIDE 224
#define P_LSTRIDE 3584  // 224*16 halfs per point

// Scratch (allocation-free rule: device globals; zero-initialized)
__device__ float g_qkv[(size_t)NPTS * 768];
__device__ float g_mid[(size_t)NPTS * CDIM];
__device__ __align__(16) __half g_tabh[T_VTOT];
__device__ __align__(16) __half g_ctk[16 * CT_LSTRIDE * 16];
__device__ __align__(16) __half g_ctq[16 * CT_LSTRIDE * 16];
__device__ __align__(16) __half g_qh[(size_t)NPTS * 256];
__device__ __align__(16) __half g_kh[(size_t)NPTS * 256];
__device__ __align__(16) __half g_pq[(size_t)NPTS * P_LSTRIDE];
__device__ __align__(16) __half g_pk[(size_t)NPTS * P_LSTRIDE];

// packed f32x2 FMA
#define FMA2(c, a, b) \
    asm("fma.rn.f32x2 %0, %1, %2, %0;" : "+l"(c) : "l"(a), "l"(b))

// ---------------------------------------------------------------------------
// Table conversion: combined logit tables [h][dl][c] + transposed value tables
// ---------------------------------------------------------------------------
__global__ void cvt_tabs(const float* __restrict__ kx, const float* __restrict__ qx,
                         const float* __restrict__ vx, const float* __restrict__ kr,
                         const float* __restrict__ qr, const float* __restrict__ vr)
{
    int i = blockIdx.x * 256 + threadIdx.x;
    // value transposed dst: [row][c8][h][8]
    int vdst = (i & ~255) | ((i & 8) << 4) | ((i & 240) >> 1) | (i & 7);
    if (i < 30720) {  // xyz: dl = i>>8 in [0,120)
        int cdst = (((i >> 4) & 15) * CT_LSTRIDE + (i >> 8)) * 16 + (i & 15);
        g_ctk[cdst] = __float2half(kx[i]);
        g_ctq[cdst] = __float2half(qx[i]);
        g_tabh[T_VX + vdst] = __float2half(vx[i]);
    }
    if (i < 24576) {  // rgb: dl = 120 + (i>>8)
        int cdst = (((i >> 4) & 15) * CT_LSTRIDE + 120 + (i >> 8)) * 16 + (i & 15);
        g_ctk[cdst] = __float2half(kr[i]);
        g_ctq[cdst] = __float2half(qr[i]);
        g_tabh[T_VR + vdst] = __float2half(vr[i]);
    }
}

// fp16 copies of q (scaled) and k for the P GEMMs
__global__ void cvt_qk()
{
    size_t pt = blockIdx.x;
    int c = threadIdx.x;
    g_qh[pt * 256 + c] = __float2half(g_qkv[pt * 768 + c] * QK_SCALE);
    g_kh[pt * 256 + c] = __float2half(g_qkv[pt * 768 + 256 + c]);
}

// ---------------------------------------------------------------------------
// Precompute PQ[point,l,h] = q.ktab[l,h], PK[point,l,h] = k.qtab[l,h]
// via wmma 16x16x16 (fp16 in, fp32 acc). One CTA = 16 points.
// ---------------------------------------------------------------------------
__global__ __launch_bounds__(256, 3) void precompute_P()
{
    __shared__ __half stage[16 * 16 * 16];   // [pt][l][h]
    __shared__ float scratch[8][256];        // per-warp C tile
    const int p0 = blockIdx.x * 16;
    const int tid = threadIdx.x;
    const int wid = tid >> 5, lid = tid & 31;

    for (int side = 0; side < 2; side++) {
        const __half* src = side ? g_kh : g_qh;
        const __half* ct  = side ? g_ctq : g_ctk;
        __half* dst = side ? g_pk : g_pq;
        for (int lt = 0; lt < 14; lt++) {
            for (int hh = wid; hh < 16; hh += 8) {
                wmma::fragment<wmma::matrix_a, 16, 16, 16, __half, wmma::row_major> a;
                wmma::fragment<wmma::matrix_b, 16, 16, 16, __half, wmma::col_major> b;
                wmma::fragment<wmma::accumulator, 16, 16, 16, float> c;
                wmma::fill_fragment(c, 0.f);
                wmma::load_matrix_sync(a, src + (size_t)p0 * 256 + hh * 16, 256);
                wmma::load_matrix_sync(b, ct + (hh * CT_LSTRIDE + lt * 16) * 16, 16);
                wmma::mma_sync(c, a, b, c);
                wmma::store_matrix_sync(scratch[wid], c, 16, wmma::mem_row_major);
                __syncwarp();
                for (int e = lid; e < 256; e += 32)
                    stage[e * 16 + hh] = __float2half(scratch[wid][e]);
                __syncwarp();
            }
            __syncthreads();
            {
                int pt = tid >> 4, l = tid & 15;
                const uint4* s = (const uint4*)&stage[(pt * 16 + l) * 16];
                uint4* d = (uint4*)&dst[(size_t)(p0 + pt) * P_LSTRIDE + (lt * 16 + l) * 16];
                d[0] = s[0];
                d[1] = s[1];
            }
            __syncthreads();
        }
    }
}

// ---------------------------------------------------------------------------
// SGEMM: C[M,N] = A[M,K] @ W[N,K]^T + bias[N]  (unchanged from round 6)
// ---------------------------------------------------------------------------
__global__ __launch_bounds__(256, 2) void sgemm_nt(
    const float* __restrict__ A, const float* __restrict__ Wm,
    const float* __restrict__ bias, float* __restrict__ Cm,
    int M, int N, int Kd)
{
    __shared__ __align__(16) float As[2][8][128];
    __shared__ __align__(16) float Bs[2][8][128];
    const int tid = threadIdx.x;
    const int tx = tid & 15;
    const int ty = tid >> 4;
    const int brow = blockIdx.y * 128;
    const int bcol = blockIdx.x * 128;
    const int lrow = tid >> 1;
    const int lcol = (tid & 1) * 4;

    const float* Ap = A + (size_t)(brow + lrow) * Kd + lcol;
    const float* Wp = Wm + (size_t)(bcol + lrow) * Kd + lcol;

    unsigned long long acc2[8][4];
#pragma unroll
    for (int m = 0; m < 8; m++)
#pragma unroll
        for (int p = 0; p < 4; p++) acc2[m][p] = 0ull;

    {
        float4 av = *(const float4*)Ap;
        float4 wv = *(const float4*)Wp;
        As[0][lcol + 0][lrow] = av.x; As[0][lcol + 1][lrow] = av.y;
        As[0][lcol + 2][lrow] = av.z; As[0][lcol + 3][lrow] = av.w;
        Bs[0][lcol + 0][lrow] = wv.x; Bs[0][lcol + 1][lrow] = wv.y;
        Bs[0][lcol + 2][lrow] = wv.z; Bs[0][lcol + 3][lrow] = wv.w;
    }
    __syncthreads();

    const int nT = Kd / 8;
    for (int n = 0; n < nT; n++) {
        const int b = n & 1;
        float4 av2, wv2;
        const bool more = (n + 1 < nT);
        if (more) {
            av2 = *(const float4*)(Ap + (n + 1) * 8);
            wv2 = *(const float4*)(Wp + (n + 1) * 8);
        }
#pragma unroll
        for (int k = 0; k < 8; k++) {
            const ulonglong2* bp = (const ulonglong2*)&Bs[b][k][tx * 8];
            ulonglong2 b01 = bp[0];
            ulonglong2 b23 = bp[1];
#pragma unroll
            for (int m = 0; m < 8; m++) {
                unsigned int ai = __float_as_uint(As[b][k][ty * 8 + m]);
                unsigned long long aa;
                asm("mov.b64 %0, {%1, %1};" : "=l"(aa) : "r"(ai));
                FMA2(acc2[m][0], aa, b01.x);
                FMA2(acc2[m][1], aa, b01.y);
                FMA2(acc2[m][2], aa, b23.x);
                FMA2(acc2[m][3], aa, b23.y);
            }
        }
        if (more) {
            const int b2 = b ^ 1;
            As[b2][lcol + 0][lrow] = av2.x; As[b2][lcol + 1][lrow] = av2.y;
            As[b2][lcol + 2][lrow] = av2.z; As[b2][lcol + 3][lrow] = av2.w;
            Bs[b2][lcol + 0][lrow] = wv2.x; Bs[b2][lcol + 1][lrow] = wv2.y;
            Bs[b2][lcol + 2][lrow] = wv2.z; Bs[b2][lcol + 3][lrow] = wv2.w;
        }
        __syncthreads();
    }

#pragma unroll
    for (int m = 0; m < 8; m++) {
        int row = brow + ty * 8 + m;
#pragma unroll
        for (int p = 0; p < 4; p += 2) {
            int col = bcol + tx * 8 + p * 2;
            float c0, c1, c2, c3;
            asm("mov.b64 {%0, %1}, %2;" : "=f"(c0), "=f"(c1) : "l"(acc2[m][p]));
            asm("mov.b64 {%0, %1}, %2;" : "=f"(c2), "=f"(c3) : "l"(acc2[m][p + 1]));
            float4 o;
            o.x = c0 + bias[col + 0];
            o.y = c1 + bias[col + 1];
            o.z = c2 + bias[col + 2];
            o.w = c3 + bias[col + 3];
            *(float4*)&Cm[(size_t)row * N + col] = o;
        }
    }
}

// ---------------------------------------------------------------------------
// Windowed attention: logit tables via precomputed PQ/PK scalar lookups;
// value tables gathered fp16; fused single pass.
// ---------------------------------------------------------------------------
struct H8 { uint4 u; };
__device__ __forceinline__ H8 ldt(const __half* __restrict__ p) {
    H8 r; r.u = *(const uint4*)p; return r;
}
__device__ __forceinline__ __half2 lane(const H8& a, int l) {
    unsigned w = (l == 0) ? a.u.x : (l == 1) ? a.u.y : (l == 2) ? a.u.z : a.u.w;
    return *reinterpret_cast<const __half2*>(&w);
}
__device__ __forceinline__ __half2 sum6(const H8& a0, const H8& a1, const H8& a2,
                                        const H8& a3, const H8& a4, const H8& a5, int l) {
    return __hadd2(__hadd2(__hadd2(lane(a0, l), lane(a1, l)),
                           __hadd2(lane(a2, l), lane(a3, l))),
                   __hadd2(lane(a4, l), lane(a5, l)));
}

// smem layout (float offsets):
//   sk     [32*320] fp32 @ 0..10240  (h-stride 20, conflict-free)
//   svh    [8192] halfs  @ 10240..14336
//   scoord [192]         @ 14336
//   spt    [32] int      @ 14528
//   sidx2  [1024] uint2  @ 14560..16608
#define ATTN_SMEM_FLOATS 16608
#define ATTN_SMEM_BYTES (ATTN_SMEM_FLOATS * 4)

__global__ __launch_bounds__(256, 3) void win_attn(
    const float* __restrict__ n_coords, const int* __restrict__ n2n)
{
    extern __shared__ float smem[];
    float* sk = smem;
    __half* svh = (__half*)(smem + 10240);
    float* scoord = smem + 14336;
    int* spt = (int*)(smem + 14528);
    uint2* sidx2 = (uint2*)(smem + 14560);

    const int tid = threadIdx.x;
    const int w = blockIdx.x;

    if (tid < KWIN) spt[tid] = n2n[w * KWIN + tid];
    __syncthreads();

    if (tid < 192) {
        int i = tid / 6, d = tid % 6;
        float s = (d < 3) ? QSF : CQSF;
        scoord[tid] = n_coords[(size_t)spt[i] * 6 + d] * s;
    }
    // stage K fp32 (padded) and V fp16
    {
        const int h = tid >> 4, c = tid & 15;
        for (int j = 0; j < KWIN; ++j) {
            size_t base = (size_t)spt[j] * 768;
            sk[j * 320 + h * 20 + c] = g_qkv[base + 256 + tid];
            svh[j * 256 + tid] = __float2half(g_qkv[base + 512 + tid]);
        }
    }
    __syncthreads();

    // packed relative indices per (i,j)
#pragma unroll
    for (int r = 0; r < 4; ++r) {
        int p = r * 256 + tid;
        int i = p >> 5, j = p & 31;
        const float* ci = scoord + i * 6;
        const float* cj = scoord + j * 6;
        int l[6];
#pragma unroll
        for (int d = 0; d < 3; d++) {
            int v = (int)floorf(ci[d] - cj[d]) + LXYZ / 2;
            l[d] = min(max(v, 0), LXYZ - 1);
        }
#pragma unroll
        for (int d = 0; d < 3; d++) {
            int v = (int)floorf(ci[3 + d] - cj[3 + d]) + LRGB / 2;
            l[3 + d] = min(max(v, 0), LRGB - 1);
        }
        unsigned lo = (unsigned)l[0] | ((unsigned)l[1] << 8) |
                      ((unsigned)l[2] << 16) | ((unsigned)l[3] << 24);
        unsigned hi = (unsigned)l[4] | ((unsigned)l[5] << 8);
        sidx2[p] = make_uint2(lo, hi);
    }
    __syncthreads();

    // each thread owns rows (i,h); 2 per thread
    for (int r = 0; r < 2; ++r) {
        const int row = r * 256 + tid;
        const int i = row >> 4;
        const int h = row & 15;
        const int hb = h * 16;
        const int pt = spt[i];

        const __half* tVX = g_tabh + T_VX + h * 8;
        const __half* tVR = g_tabh + T_VR + h * 8;
        const __half* pqi = g_pq + (size_t)pt * P_LSTRIDE + h;

        // q row (scaled) fp32
        float qf[16];
        {
            const float4* qp = (const float4*)(g_qkv + (size_t)pt * 768 + hb);
#pragma unroll
            for (int t = 0; t < 4; t++) {
                float4 v = qp[t];
                qf[t * 4 + 0] = v.x * QK_SCALE; qf[t * 4 + 1] = v.y * QK_SCALE;
                qf[t * 4 + 2] = v.z * QK_SCALE; qf[t * 4 + 3] = v.w * QK_SCALE;
            }
        }

        // softmax baseline from j=0 main dot
        float bshift = 0.f;
        {
            const float* k0 = sk + h * 20;
#pragma unroll
            for (int t = 0; t < 4; t++) {
                float4 kv = *(const float4*)(k0 + 4 * t);
                bshift += qf[4 * t + 0] * kv.x + qf[4 * t + 1] * kv.y +
                          qf[4 * t + 2] * kv.z + qf[4 * t + 3] * kv.w;
            }
        }

        float ssum = 0.f;
        float of[16];
#pragma unroll
        for (int e = 0; e < 16; e++) of[e] = 0.f;

        for (int j = 0; j < KWIN; ++j) {
            const uint2 pk = sidx2[i * 32 + j];
            const int i0 = (int)(pk.x & 255), i1 = (int)((pk.x >> 8) & 255),
                      i2 = (int)((pk.x >> 16) & 255), i3 = (int)(pk.x >> 24),
                      i4 = (int)(pk.y & 255), i5 = (int)((pk.y >> 8) & 255);

            // fp32 main q.k dot from smem
            const float* kj = sk + j * 320 + h * 20;
            float facc = 0.f;
#pragma unroll
            for (int t = 0; t < 4; t++) {
                float4 kv = *(const float4*)(kj + 4 * t);
                facc += qf[4 * t + 0] * kv.x + qf[4 * t + 1] * kv.y +
                        qf[4 * t + 2] * kv.z + qf[4 * t + 3] * kv.w;
            }

            // precomputed table logits: 12 scalar fp16 lookups
            {
                const __half* pkj = g_pk + (size_t)spt[j] * P_LSTRIDE + h;
                const int pA = i0 << 4, pB = (40 + i1) << 4, pC = (80 + i2) << 4,
                          pD = (120 + i3) << 4, pE = (152 + i4) << 4, pF = (184 + i5) << 4;
                facc += __half2float(pqi[pA]) + __half2float(pqi[pB]) +
                        __half2float(pqi[pC]) + __half2float(pqi[pD]) +
                        __half2float(pqi[pE]) + __half2float(pqi[pF]) +
                        __half2float(pkj[pA]) + __half2float(pkj[pB]) +
                        __half2float(pkj[pC]) + __half2float(pkj[pD]) +
                        __half2float(pkj[pE]) + __half2float(pkj[pF]);
            }

            const float a = __expf(facc - bshift);
            ssum += a;

            // value side: a * (v + sum of 6 gathered value-table rows)
            const int r0 = i0 << 8, r1 = (40 + i1) << 8, r2 = (80 + i2) << 8;
            const int r3 = i3 << 8, r4 = (32 + i4) << 8, r5 = (64 + i5) << 8;
            H8 vva = ldt(svh + j * 256 + hb);
            H8 vvb = ldt(svh + j * 256 + hb + 8);
#pragma unroll
            for (int c = 0; c < 2; c++) {
                const int co = c << 7;
                H8 v0 = ldt(tVX + r0 + co), v1 = ldt(tVX + r1 + co),
                   v2 = ldt(tVX + r2 + co), v3 = ldt(tVR + r3 + co),
                   v4 = ldt(tVR + r4 + co), v5 = ldt(tVR + r5 + co);
                const H8& vv = c ? vvb : vva;
                float* o = of + c * 8;
#pragma unroll
                for (int l = 0; l < 4; l++) {
                    float2 vf = __half22float2(lane(vv, l));
                    float2 tf = __half22float2(sum6(v0, v1, v2, v3, v4, v5, l));
                    o[2 * l + 0] += a * (vf.x + tf.x);
                    o[2 * l + 1] += a * (vf.y + tf.y);
                }
            }
        }

        const float inv = 1.0f / ssum;
        float4* op = (float4*)(g_mid + (size_t)pt * CDIM + hb);
#pragma unroll
        for (int t = 0; t < 4; t++)
            op[t] = make_float4(of[4 * t] * inv, of[4 * t + 1] * inv,
                                of[4 * t + 2] * inv, of[4 * t + 3] * inv);
    }
}

// ---------------------------------------------------------------------------
extern "C" void kernel_launch(void* const* d_in, const int* in_sizes, int n_in,
                              void* d_out, int out_size)
{
    const float* feats    = (const float*)d_in[0];
    const float* n_coords = (const float*)d_in[1];
    const int*   n2n      = (const int*)d_in[2];
    const float* q_xyz    = (const float*)d_in[3];
    const float* k_xyz    = (const float*)d_in[4];
    const float* v_xyz    = (const float*)d_in[5];
    const float* q_rgb    = (const float*)d_in[6];
    const float* k_rgb    = (const float*)d_in[7];
    const float* v_rgb    = (const float*)d_in[8];
    const float* qkv_w    = (const float*)d_in[9];
    const float* qkv_b    = (const float*)d_in[10];
    const float* proj_w   = (const float*)d_in[11];
    const float* proj_b   = (const float*)d_in[12];
    float* out = (float*)d_out;

    float *qkv_p = nullptr, *mid_p = nullptr;
    cudaGetSymbolAddress((void**)&qkv_p, g_qkv);
    cudaGetSymbolAddress((void**)&mid_p, g_mid);

    cudaFuncSetAttribute(win_attn, cudaFuncAttributeMaxDynamicSharedMemorySize,
                         ATTN_SMEM_BYTES);

    // 0) table conversion (independent of GEMM)
    cvt_tabs<<<120, 256>>>(k_xyz, q_xyz, v_xyz, k_rgb, q_rgb, v_rgb);

    // 1) QKV projection
    dim3 g1(768 / 128, NPTS / 128);
    sgemm_nt<<<g1, 256>>>(feats, qkv_w, qkv_b, qkv_p, NPTS, 768, CDIM);

    // 2) fp16 copies of q(scaled)/k, then P-table GEMMs
    cvt_qk<<<NPTS, 256>>>();
    precompute_P<<<NPTS / 16, 256>>>();

    // 3) windowed attention (fused)
    win_attn<<<NWIN, 256, ATTN_SMEM_BYTES>>>(n_coords, n2n);

    // 4) output projection
    dim3 g2(CDIM / 128, NPTS / 128);
    sgemm_nt<<<g2, 256>>>(mid_p, proj_w, proj_b, out, NPTS, CDIM, CDIM);
}

// round 9
// speedup vs baseline: 1.6331x; 1.6331x over previous
#include <cuda_runtime.h>
#include <cuda_fp16.h>
#include <mma.h>
#include <math.h>

using namespace nvcuda;

#define NPTS 65536
#define CDIM 256
#define KWIN 32
#define NWIN 2048
#define LXYZ 40
#define LRGB 32
#define QSF 4.0f
#define CQSF 8.0f
#define QK_SCALE 0.25f

// half-table layout offsets (in halfs). Row layout TRANSPOSED: [row][c][h][8]
#define T_KX 0
#define T_QX 30720
#define T_VX 61440
#define T_KR 92160
#define T_QR 116736
#define T_VR 141312
#define T_TOT 165888

// Scratch (allocation-free rule: device globals)
__device__ float g_qkv[(size_t)NPTS * 768];
__device__ float g_mid[(size_t)NPTS * CDIM];
__device__ __align__(16) __half g_tabh[T_TOT];

// ---------------------------------------------------------------------------
// Convert fp32 tables to fp16 with transposed row layout [row][c][h][8halfs]
// ---------------------------------------------------------------------------
__global__ void cvt_tabs(const float* __restrict__ kx, const float* __restrict__ qx,
                         const float* __restrict__ vx, const float* __restrict__ kr,
                         const float* __restrict__ qr, const float* __restrict__ vr)
{
    int i = blockIdx.x * 256 + threadIdx.x;
    int dst = (i & ~255) | ((i & 8) << 4) | ((i & 240) >> 1) | (i & 7);
    if (i < 30720) {
        g_tabh[T_KX + dst] = __float2half(kx[i]);
        g_tabh[T_QX + dst] = __float2half(qx[i]);
        g_tabh[T_VX + dst] = __float2half(vx[i]);
    }
    if (i < 24576) {
        g_tabh[T_KR + dst] = __float2half(kr[i]);
        g_tabh[T_QR + dst] = __float2half(qr[i]);
        g_tabh[T_VR + dst] = __float2half(vr[i]);
    }
}

// ---------------------------------------------------------------------------
// tf32 tensor-core GEMM: C[M,N] = A[M,K] @ W[N,K]^T + bias[N]
// 128x128 CTA tile, 8 warps x (32x64), BK=16, reg-prefetch double buffer.
// ---------------------------------------------------------------------------
__global__ __launch_bounds__(256, 2) void gemm_tf32(
    const float* __restrict__ A, const float* __restrict__ Wm,
    const float* __restrict__ bias, float* __restrict__ Cm,
    int M, int N, int Kd)
{
    __shared__ __align__(16) float As[2][128 * 16];
    __shared__ __align__(16) float Bs[2][128 * 16];
    __shared__ __align__(16) float scratch[8][256];

    const int tid = threadIdx.x;
    const int wid = tid >> 5;
    const int lane = tid & 31;
    const int brow = blockIdx.y * 128;
    const int bcol = blockIdx.x * 128;
    const int m0 = (wid >> 1) * 32;
    const int n0 = (wid & 1) * 64;

    // loader mapping: 256 threads x 8 floats = 128x16 tile
    const int lrow = tid >> 1;
    const int lcb = (tid & 1) * 8;
    const float* Ap = A + (size_t)(brow + lrow) * Kd + lcb;
    const float* Wp = Wm + (size_t)(bcol + lrow) * Kd + lcb;

    wmma::fragment<wmma::accumulator, 16, 16, 8, float> acc[2][4];
#pragma unroll
    for (int mi = 0; mi < 2; mi++)
#pragma unroll
        for (int ni = 0; ni < 4; ni++) wmma::fill_fragment(acc[mi][ni], 0.f);

    // prologue: tile 0
    {
        float4 a0 = *(const float4*)Ap;
        float4 a1 = *(const float4*)(Ap + 4);
        float4 w0 = *(const float4*)Wp;
        float4 w1 = *(const float4*)(Wp + 4);
        *(float4*)&As[0][lrow * 16 + lcb] = a0;
        *(float4*)&As[0][lrow * 16 + lcb + 4] = a1;
        *(float4*)&Bs[0][lrow * 16 + lcb] = w0;
        *(float4*)&Bs[0][lrow * 16 + lcb + 4] = w1;
    }
    __syncthreads();

    const int nT = Kd / 16;
    for (int kt = 0; kt < nT; kt++) {
        const int buf = kt & 1;
        float4 a0, a1, w0, w1;
        const bool more = (kt + 1 < nT);
        if (more) {
            a0 = *(const float4*)(Ap + (kt + 1) * 16);
            a1 = *(const float4*)(Ap + (kt + 1) * 16 + 4);
            w0 = *(const float4*)(Wp + (kt + 1) * 16);
            w1 = *(const float4*)(Wp + (kt + 1) * 16 + 4);
        }
#pragma unroll
        for (int ks = 0; ks < 2; ks++) {
            wmma::fragment<wmma::matrix_a, 16, 16, 8, wmma::precision::tf32,
                           wmma::row_major> af[2];
            wmma::fragment<wmma::matrix_b, 16, 16, 8, wmma::precision::tf32,
                           wmma::col_major> bf[4];
#pragma unroll
            for (int mi = 0; mi < 2; mi++) {
                wmma::load_matrix_sync(af[mi],
                    &As[buf][(m0 + 16 * mi) * 16 + ks * 8], 16);
#pragma unroll
                for (int t = 0; t < af[mi].num_elements; t++)
                    af[mi].x[t] = wmma::__float_to_tf32(af[mi].x[t]);
            }
#pragma unroll
            for (int ni = 0; ni < 4; ni++) {
                wmma::load_matrix_sync(bf[ni],
                    &Bs[buf][(n0 + 16 * ni) * 16 + ks * 8], 16);
#pragma unroll
                for (int t = 0; t < bf[ni].num_elements; t++)
                    bf[ni].x[t] = wmma::__float_to_tf32(bf[ni].x[t]);
            }
#pragma unroll
            for (int mi = 0; mi < 2; mi++)
#pragma unroll
                for (int ni = 0; ni < 4; ni++)
                    wmma::mma_sync(acc[mi][ni], af[mi], bf[ni], acc[mi][ni]);
        }
        if (more) {
            const int b2 = buf ^ 1;
            *(float4*)&As[b2][lrow * 16 + lcb] = a0;
            *(float4*)&As[b2][lrow * 16 + lcb + 4] = a1;
            *(float4*)&Bs[b2][lrow * 16 + lcb] = w0;
            *(float4*)&Bs[b2][lrow * 16 + lcb + 4] = w1;
        }
        __syncthreads();
    }

    // epilogue: per-warp scratch, add bias, write out
#pragma unroll
    for (int mi = 0; mi < 2; mi++) {
#pragma unroll
        for (int ni = 0; ni < 4; ni++) {
            wmma::store_matrix_sync(scratch[wid], acc[mi][ni], 16,
                                    wmma::mem_row_major);
            __syncwarp();
#pragma unroll
            for (int e = 0; e < 8; e++) {
                int id = e * 32 + lane;
                int rr = id >> 4, cc = id & 15;
                int col = bcol + n0 + 16 * ni + cc;
                Cm[(size_t)(brow + m0 + 16 * mi + rr) * N + col] =
                    scratch[wid][rr * 16 + cc] + __ldg(&bias[col]);
            }
            __syncwarp();
        }
    }
}

// ---------------------------------------------------------------------------
// Windowed attention (round-6 version: fp32 K + half K copy, fp32 V, fused)
// ---------------------------------------------------------------------------
struct H8 { uint4 u; };
__device__ __forceinline__ H8 ldt(const __half* __restrict__ p) {
    H8 r; r.u = *(const uint4*)p; return r;
}
__device__ __forceinline__ __half2 lane(const H8& a, int l) {
    unsigned w = (l == 0) ? a.u.x : (l == 1) ? a.u.y : (l == 2) ? a.u.z : a.u.w;
    return *reinterpret_cast<const __half2*>(&w);
}
__device__ __forceinline__ __half2 sum6(const H8& a0, const H8& a1, const H8& a2,
                                        const H8& a3, const H8& a4, const H8& a5, int l) {
    return __hadd2(__hadd2(__hadd2(lane(a0, l), lane(a1, l)),
                           __hadd2(lane(a2, l), lane(a3, l))),
                   __hadd2(lane(a4, l), lane(a5, l)));
}

// smem layout (float offsets):
//   sk     [32*320] @ 0       (fp32 K, h-stride 20 -> conflict-free LDS.128)
//   sv     [32*320] @ 10240   (fp32 V, same padding)
//   scoord [192]    @ 20480
//   spt    [32] int @ 20672
//   sidx2  [1024]u2 @ 20704   (2048 floats, ends 22752)
//   skh    [8192]h  @ 22752   (4096 floats, ends 26848)
#define ATTN_SMEM_FLOATS 26848
#define ATTN_SMEM_BYTES (ATTN_SMEM_FLOATS * 4)

__global__ __launch_bounds__(256, 2) void win_attn(
    const float* __restrict__ n_coords, const int* __restrict__ n2n)
{
    extern __shared__ float smem[];
    float* sk = smem;
    float* sv = smem + 10240;
    float* scoord = smem + 20480;
    int* spt = (int*)(smem + 20672);
    uint2* sidx2 = (uint2*)(smem + 20704);
    __half* skh = (__half*)(smem + 22752);

    const int tid = threadIdx.x;
    const int w = blockIdx.x;

    if (tid < KWIN) spt[tid] = n2n[w * KWIN + tid];
    __syncthreads();

    if (tid < 192) {
        int i = tid / 6, d = tid % 6;
        float s = (d < 3) ? QSF : CQSF;
        scoord[tid] = n_coords[(size_t)spt[i] * 6 + d] * s;
    }
    {
        const int h = tid >> 4, c = tid & 15;
        for (int j = 0; j < KWIN; ++j) {
            size_t base = (size_t)spt[j] * 768;
            float kv = g_qkv[base + 256 + tid];
            float vv = g_qkv[base + 512 + tid];
            sk[j * 320 + h * 20 + c] = kv;
            sv[j * 320 + h * 20 + c] = vv;
            skh[j * 256 + tid] = __float2half(kv);
        }
    }
    __syncthreads();

#pragma unroll
    for (int r = 0; r < 4; ++r) {
        int p = r * 256 + tid;
        int i = p >> 5, j = p & 31;
        const float* ci = scoord + i * 6;
        const float* cj = scoord + j * 6;
        int l[6];
#pragma unroll
        for (int d = 0; d < 3; d++) {
            int v = (int)floorf(ci[d] - cj[d]) + LXYZ / 2;
            l[d] = min(max(v, 0), LXYZ - 1);
        }
#pragma unroll
        for (int d = 0; d < 3; d++) {
            int v = (int)floorf(ci[3 + d] - cj[3 + d]) + LRGB / 2;
            l[3 + d] = min(max(v, 0), LRGB - 1);
        }
        unsigned lo = (unsigned)l[0] | ((unsigned)l[1] << 8) |
                      ((unsigned)l[2] << 16) | ((unsigned)l[3] << 24);
        unsigned hi = (unsigned)l[4] | ((unsigned)l[5] << 8);
        sidx2[p] = make_uint2(lo, hi);
    }
    __syncthreads();

    for (int r = 0; r < 2; ++r) {
        const int row = r * 256 + tid;
        const int i = row >> 4;
        const int h = row & 15;
        const int hb = h * 16;
        const int h8 = h * 8;
        const int pt = spt[i];

        const __half* tKX = g_tabh + T_KX + h8;
        const __half* tQX = g_tabh + T_QX + h8;
        const __half* tVX = g_tabh + T_VX + h8;
        const __half* tKR = g_tabh + T_KR + h8;
        const __half* tQR = g_tabh + T_QR + h8;
        const __half* tVR = g_tabh + T_VR + h8;

        float qf[16];
        __half2 qh[8];
        {
            const float4* qp = (const float4*)(g_qkv + (size_t)pt * 768 + hb);
#pragma unroll
            for (int t = 0; t < 4; t++) {
                float4 v = qp[t];
                qf[t * 4 + 0] = v.x * QK_SCALE; qf[t * 4 + 1] = v.y * QK_SCALE;
                qf[t * 4 + 2] = v.z * QK_SCALE; qf[t * 4 + 3] = v.w * QK_SCALE;
            }
#pragma unroll
            for (int k = 0; k < 8; k++)
                qh[k] = __floats2half2_rn(qf[2 * k], qf[2 * k + 1]);
        }

        float bshift = 0.f;
        {
            const float* k0 = sk + h * 20;
#pragma unroll
            for (int t = 0; t < 4; t++) {
                float4 kv = *(const float4*)(k0 + 4 * t);
                bshift += qf[4 * t + 0] * kv.x + qf[4 * t + 1] * kv.y +
                          qf[4 * t + 2] * kv.z + qf[4 * t + 3] * kv.w;
            }
        }

        float ssum = 0.f;
        float of[16];
#pragma unroll
        for (int e = 0; e < 16; e++) of[e] = 0.f;

        for (int j = 0; j < KWIN; ++j) {
            const uint2 pk = sidx2[i * 32 + j];
            const int r0 = (int)(pk.x & 255) << 8;
            const int r1 = (int)(40 + ((pk.x >> 8) & 255)) << 8;
            const int r2 = (int)(80 + ((pk.x >> 16) & 255)) << 8;
            const int r3 = (int)(pk.x >> 24) << 8;
            const int r4 = (int)(32 + (pk.y & 255)) << 8;
            const int r5 = (int)(64 + ((pk.y >> 8) & 255)) << 8;

            const float* kj = sk + j * 320 + h * 20;
            float facc = 0.f;
#pragma unroll
            for (int t = 0; t < 4; t++) {
                float4 kv = *(const float4*)(kj + 4 * t);
                facc += qf[4 * t + 0] * kv.x + qf[4 * t + 1] * kv.y +
                        qf[4 * t + 2] * kv.z + qf[4 * t + 3] * kv.w;
            }

            const __half* khp = skh + j * 256 + hb;
#pragma unroll
            for (int c = 0; c < 2; c++) {
                const int co = c << 7;
                H8 a0 = ldt(tKX + r0 + co), a1 = ldt(tKX + r1 + co),
                   a2 = ldt(tKX + r2 + co), a3 = ldt(tKR + r3 + co),
                   a4 = ldt(tKR + r4 + co), a5 = ldt(tKR + r5 + co);
                H8 b0 = ldt(tQX + r0 + co), b1 = ldt(tQX + r1 + co),
                   b2 = ldt(tQX + r2 + co), b3 = ldt(tQR + r3 + co),
                   b4 = ldt(tQR + r4 + co), b5 = ldt(tQR + r5 + co);
                H8 kk = ldt(khp + 8 * c);
                __half2 hq = __float2half2_rn(0.f);
                __half2 hk = hq;
#pragma unroll
                for (int l = 0; l < 4; l++) {
                    __half2 qs = sum6(a0, a1, a2, a3, a4, a5, l);
                    __half2 ks = sum6(b0, b1, b2, b3, b4, b5, l);
                    hq = __hfma2(qh[c * 4 + l], qs, hq);
                    hk = __hfma2(lane(kk, l), ks, hk);
                }
                float2 f = __half22float2(__hadd2(hq, hk));
                facc += f.x + f.y;
            }

            const float a = __expf(facc - bshift);
            ssum += a;

            const float* vj = sv + j * 320 + h * 20;
#pragma unroll
            for (int c = 0; c < 2; c++) {
                const int co = c << 7;
                H8 v0 = ldt(tVX + r0 + co), v1 = ldt(tVX + r1 + co),
                   v2 = ldt(tVX + r2 + co), v3 = ldt(tVR + r3 + co),
                   v4 = ldt(tVR + r4 + co), v5 = ldt(tVR + r5 + co);
                float4 va = *(const float4*)(vj + 8 * c);
                float4 vb = *(const float4*)(vj + 8 * c + 4);
                float2 t0 = __half22float2(sum6(v0, v1, v2, v3, v4, v5, 0));
                float2 t1 = __half22float2(sum6(v0, v1, v2, v3, v4, v5, 1));
                float2 t2 = __half22float2(sum6(v0, v1, v2, v3, v4, v5, 2));
                float2 t3 = __half22float2(sum6(v0, v1, v2, v3, v4, v5, 3));
                float* o = of + c * 8;
                o[0] += a * (va.x + t0.x); o[1] += a * (va.y + t0.y);
                o[2] += a * (va.z + t1.x); o[3] += a * (va.w + t1.y);
                o[4] += a * (vb.x + t2.x); o[5] += a * (vb.y + t2.y);
                o[6] += a * (vb.z + t3.x); o[7] += a * (vb.w + t3.y);
            }
        }

        const float inv = 1.0f / ssum;
        float4* op = (float4*)(g_mid + (size_t)pt * CDIM + hb);
#pragma unroll
        for (int t = 0; t < 4; t++)
            op[t] = make_float4(of[4 * t] * inv, of[4 * t + 1] * inv,
                                of[4 * t + 2] * inv, of[4 * t + 3] * inv);
    }
}

// ---------------------------------------------------------------------------
extern "C" void kernel_launch(void* const* d_in, const int* in_sizes, int n_in,
                              void* d_out, int out_size)
{
    const float* feats    = (const float*)d_in[0];
    const float* n_coords = (const float*)d_in[1];
    const int*   n2n      = (const int*)d_in[2];
    const float* q_xyz    = (const float*)d_in[3];
    const float* k_xyz    = (const float*)d_in[4];
    const float* v_xyz    = (const float*)d_in[5];
    const float* q_rgb    = (const float*)d_in[6];
    const float* k_rgb    = (const float*)d_in[7];
    const float* v_rgb    = (const float*)d_in[8];
    const float* qkv_w    = (const float*)d_in[9];
    const float* qkv_b    = (const float*)d_in[10];
    const float* proj_w   = (const float*)d_in[11];
    const float* proj_b   = (const float*)d_in[12];
    float* out = (float*)d_out;

    float *qkv_p = nullptr, *mid_p = nullptr;
    cudaGetSymbolAddress((void**)&qkv_p, g_qkv);
    cudaGetSymbolAddress((void**)&mid_p, g_mid);

    cudaFuncSetAttribute(win_attn, cudaFuncAttributeMaxDynamicSharedMemorySize,
                         ATTN_SMEM_BYTES);

    // 0) convert tables to fp16 (transposed rows)
    cvt_tabs<<<120, 256>>>(k_xyz, q_xyz, v_xyz, k_rgb, q_rgb, v_rgb);

    // 1) QKV projection: [65536,256] x [768,256]^T  (tf32 tensor cores)
    dim3 g1(768 / 128, NPTS / 128);
    gemm_tf32<<<g1, 256>>>(feats, qkv_w, qkv_b, qkv_p, NPTS, 768, CDIM);

    // 2) windowed attention (fused)
    win_attn<<<NWIN, 256, ATTN_SMEM_BYTES>>>(n_coords, n2n);

    // 3) output projection: [65536,256] x [256,256]^T  (tf32 tensor cores)
    dim3 g2(CDIM / 128, NPTS / 128);
    gemm_tf32<<<g2, 256>>>(mid_p, proj_w, proj_b, out, NPTS, CDIM, CDIM);
}

// round 10
// speedup vs baseline: 1.7850x; 1.0930x over previous
#include <cuda_runtime.h>
#include <cuda_fp16.h>
#include <mma.h>
#include <math.h>

using namespace nvcuda;

#define NPTS 65536
#define CDIM 256
#define KWIN 32
#define NWIN 2048
#define LXYZ 40
#define LRGB 32
#define QSF 4.0f
#define CQSF 8.0f
#define QK_SCALE 0.25f

// half-table layout offsets (in halfs). Row layout TRANSPOSED: [row][c][h][8]
#define T_KX 0
#define T_QX 30720
#define T_VX 61440
#define T_KR 92160
#define T_QR 116736
#define T_VR 141312
#define T_TOT 165888

// Scratch (allocation-free rule: device globals)
__device__ float g_qkv[(size_t)NPTS * 768];
__device__ float g_mid[(size_t)NPTS * CDIM];
__device__ __align__(16) __half g_tabh[T_TOT];

// ---------------------------------------------------------------------------
// Convert fp32 tables to fp16 with transposed row layout [row][c][h][8halfs]
// ---------------------------------------------------------------------------
__global__ void cvt_tabs(const float* __restrict__ kx, const float* __restrict__ qx,
                         const float* __restrict__ vx, const float* __restrict__ kr,
                         const float* __restrict__ qr, const float* __restrict__ vr)
{
    int i = blockIdx.x * 256 + threadIdx.x;
    int dst = (i & ~255) | ((i & 8) << 4) | ((i & 240) >> 1) | (i & 7);
    if (i < 30720) {
        g_tabh[T_KX + dst] = __float2half(kx[i]);
        g_tabh[T_QX + dst] = __float2half(qx[i]);
        g_tabh[T_VX + dst] = __float2half(vx[i]);
    }
    if (i < 24576) {
        g_tabh[T_KR + dst] = __float2half(kr[i]);
        g_tabh[T_QR + dst] = __float2half(qr[i]);
        g_tabh[T_VR + dst] = __float2half(vr[i]);
    }
}

// ---------------------------------------------------------------------------
// tf32 tensor-core GEMM: C[M,N] = A[M,K] @ W[N,K]^T + bias[N]
// 128x128 CTA tile, 8 warps x (32x64), BK=16, reg-prefetch double buffer.
// smem tiles padded to stride 20 floats (conflict-staggered fragment loads),
// values pre-rounded to tf32 at store time (no in-loop converts).
// ---------------------------------------------------------------------------
#define GS 20   // padded smem row stride (floats)

__global__ __launch_bounds__(256, 2) void gemm_tf32(
    const float* __restrict__ A, const float* __restrict__ Wm,
    const float* __restrict__ bias, float* __restrict__ Cm,
    int M, int N, int Kd)
{
    __shared__ __align__(16) float As[2][128 * GS];
    __shared__ __align__(16) float Bs[2][128 * GS];
    __shared__ __align__(16) float scratch[8][256];

    const int tid = threadIdx.x;
    const int wid = tid >> 5;
    const int lane = tid & 31;
    const int brow = blockIdx.y * 128;
    const int bcol = blockIdx.x * 128;
    const int m0 = (wid >> 1) * 32;
    const int n0 = (wid & 1) * 64;

    // loader mapping: 256 threads x 8 floats = 128x16 tile
    const int lrow = tid >> 1;
    const int lcb = (tid & 1) * 8;
    const float* Ap = A + (size_t)(brow + lrow) * Kd + lcb;
    const float* Wp = Wm + (size_t)(bcol + lrow) * Kd + lcb;

    wmma::fragment<wmma::accumulator, 16, 16, 8, float> acc[2][4];
#pragma unroll
    for (int mi = 0; mi < 2; mi++)
#pragma unroll
        for (int ni = 0; ni < 4; ni++) wmma::fill_fragment(acc[mi][ni], 0.f);

    // tf32-round a float4
#define R4(v) do { \
        (v).x = wmma::__float_to_tf32((v).x); \
        (v).y = wmma::__float_to_tf32((v).y); \
        (v).z = wmma::__float_to_tf32((v).z); \
        (v).w = wmma::__float_to_tf32((v).w); } while (0)

    // prologue: tile 0
    {
        float4 a0 = *(const float4*)Ap;
        float4 a1 = *(const float4*)(Ap + 4);
        float4 w0 = *(const float4*)Wp;
        float4 w1 = *(const float4*)(Wp + 4);
        R4(a0); R4(a1); R4(w0); R4(w1);
        *(float4*)&As[0][lrow * GS + lcb] = a0;
        *(float4*)&As[0][lrow * GS + lcb + 4] = a1;
        *(float4*)&Bs[0][lrow * GS + lcb] = w0;
        *(float4*)&Bs[0][lrow * GS + lcb + 4] = w1;
    }
    __syncthreads();

    const int nT = Kd / 16;
    for (int kt = 0; kt < nT; kt++) {
        const int buf = kt & 1;
        float4 a0, a1, w0, w1;
        const bool more = (kt + 1 < nT);
        if (more) {
            a0 = *(const float4*)(Ap + (kt + 1) * 16);
            a1 = *(const float4*)(Ap + (kt + 1) * 16 + 4);
            w0 = *(const float4*)(Wp + (kt + 1) * 16);
            w1 = *(const float4*)(Wp + (kt + 1) * 16 + 4);
        }
#pragma unroll
        for (int ks = 0; ks < 2; ks++) {
            wmma::fragment<wmma::matrix_a, 16, 16, 8, wmma::precision::tf32,
                           wmma::row_major> af[2];
            wmma::fragment<wmma::matrix_b, 16, 16, 8, wmma::precision::tf32,
                           wmma::col_major> bf[4];
#pragma unroll
            for (int mi = 0; mi < 2; mi++)
                wmma::load_matrix_sync(af[mi],
                    &As[buf][(m0 + 16 * mi) * GS + ks * 8], GS);
#pragma unroll
            for (int ni = 0; ni < 4; ni++)
                wmma::load_matrix_sync(bf[ni],
                    &Bs[buf][(n0 + 16 * ni) * GS + ks * 8], GS);
#pragma unroll
            for (int mi = 0; mi < 2; mi++)
#pragma unroll
                for (int ni = 0; ni < 4; ni++)
                    wmma::mma_sync(acc[mi][ni], af[mi], bf[ni], acc[mi][ni]);
        }
        if (more) {
            const int b2 = buf ^ 1;
            R4(a0); R4(a1); R4(w0); R4(w1);
            *(float4*)&As[b2][lrow * GS + lcb] = a0;
            *(float4*)&As[b2][lrow * GS + lcb + 4] = a1;
            *(float4*)&Bs[b2][lrow * GS + lcb] = w0;
            *(float4*)&Bs[b2][lrow * GS + lcb + 4] = w1;
        }
        __syncthreads();
    }
#undef R4

    // epilogue: per-warp scratch, add bias, write out
#pragma unroll
    for (int mi = 0; mi < 2; mi++) {
#pragma unroll
        for (int ni = 0; ni < 4; ni++) {
            wmma::store_matrix_sync(scratch[wid], acc[mi][ni], 16,
                                    wmma::mem_row_major);
            __syncwarp();
#pragma unroll
            for (int e = 0; e < 8; e++) {
                int id = e * 32 + lane;
                int rr = id >> 4, cc = id & 15;
                int col = bcol + n0 + 16 * ni + cc;
                Cm[(size_t)(brow + m0 + 16 * mi + rr) * N + col] =
                    scratch[wid][rr * 16 + cc] + __ldg(&bias[col]);
            }
            __syncwarp();
        }
    }
}

// ---------------------------------------------------------------------------
// Windowed attention (round-6 version: fp32 K + half K copy, fp32 V, fused)
// ---------------------------------------------------------------------------
struct H8 { uint4 u; };
__device__ __forceinline__ H8 ldt(const __half* __restrict__ p) {
    H8 r; r.u = *(const uint4*)p; return r;
}
__device__ __forceinline__ __half2 lane(const H8& a, int l) {
    unsigned w = (l == 0) ? a.u.x : (l == 1) ? a.u.y : (l == 2) ? a.u.z : a.u.w;
    return *reinterpret_cast<const __half2*>(&w);
}
__device__ __forceinline__ __half2 sum6(const H8& a0, const H8& a1, const H8& a2,
                                        const H8& a3, const H8& a4, const H8& a5, int l) {
    return __hadd2(__hadd2(__hadd2(lane(a0, l), lane(a1, l)),
                           __hadd2(lane(a2, l), lane(a3, l))),
                   __hadd2(lane(a4, l), lane(a5, l)));
}

// smem layout (float offsets):
//   sk     [32*320] @ 0       (fp32 K, h-stride 20 -> conflict-free LDS.128)
//   sv     [32*320] @ 10240   (fp32 V, same padding)
//   scoord [192]    @ 20480
//   spt    [32] int @ 20672
//   sidx2  [1024]u2 @ 20704   (2048 floats, ends 22752)
//   skh    [8192]h  @ 22752   (4096 floats, ends 26848)
#define ATTN_SMEM_FLOATS 26848
#define ATTN_SMEM_BYTES (ATTN_SMEM_FLOATS * 4)

__global__ __launch_bounds__(256, 2) void win_attn(
    const float* __restrict__ n_coords, const int* __restrict__ n2n)
{
    extern __shared__ float smem[];
    float* sk = smem;
    float* sv = smem + 10240;
    float* scoord = smem + 20480;
    int* spt = (int*)(smem + 20672);
    uint2* sidx2 = (uint2*)(smem + 20704);
    __half* skh = (__half*)(smem + 22752);

    const int tid = threadIdx.x;
    const int w = blockIdx.x;

    if (tid < KWIN) spt[tid] = n2n[w * KWIN + tid];
    __syncthreads();

    if (tid < 192) {
        int i = tid / 6, d = tid % 6;
        float s = (d < 3) ? QSF : CQSF;
        scoord[tid] = n_coords[(size_t)spt[i] * 6 + d] * s;
    }
    {
        const int h = tid >> 4, c = tid & 15;
        for (int j = 0; j < KWIN; ++j) {
            size_t base = (size_t)spt[j] * 768;
            float kv = g_qkv[base + 256 + tid];
            float vv = g_qkv[base + 512 + tid];
            sk[j * 320 + h * 20 + c] = kv;
            sv[j * 320 + h * 20 + c] = vv;
            skh[j * 256 + tid] = __float2half(kv);
        }
    }
    __syncthreads();

#pragma unroll
    for (int r = 0; r < 4; ++r) {
        int p = r * 256 + tid;
        int i = p >> 5, j = p & 31;
        const float* ci = scoord + i * 6;
        const float* cj = scoord + j * 6;
        int l[6];
#pragma unroll
        for (int d = 0; d < 3; d++) {
            int v = (int)floorf(ci[d] - cj[d]) + LXYZ / 2;
            l[d] = min(max(v, 0), LXYZ - 1);
        }
#pragma unroll
        for (int d = 0; d < 3; d++) {
            int v = (int)floorf(ci[3 + d] - cj[3 + d]) + LRGB / 2;
            l[3 + d] = min(max(v, 0), LRGB - 1);
        }
        unsigned lo = (unsigned)l[0] | ((unsigned)l[1] << 8) |
                      ((unsigned)l[2] << 16) | ((unsigned)l[3] << 24);
        unsigned hi = (unsigned)l[4] | ((unsigned)l[5] << 8);
        sidx2[p] = make_uint2(lo, hi);
    }
    __syncthreads();

    for (int r = 0; r < 2; ++r) {
        const int row = r * 256 + tid;
        const int i = row >> 4;
        const int h = row & 15;
        const int hb = h * 16;
        const int h8 = h * 8;
        const int pt = spt[i];

        const __half* tKX = g_tabh + T_KX + h8;
        const __half* tQX = g_tabh + T_QX + h8;
        const __half* tVX = g_tabh + T_VX + h8;
        const __half* tKR = g_tabh + T_KR + h8;
        const __half* tQR = g_tabh + T_QR + h8;
        const __half* tVR = g_tabh + T_VR + h8;

        float qf[16];
        __half2 qh[8];
        {
            const float4* qp = (const float4*)(g_qkv + (size_t)pt * 768 + hb);
#pragma unroll
            for (int t = 0; t < 4; t++) {
                float4 v = qp[t];
                qf[t * 4 + 0] = v.x * QK_SCALE; qf[t * 4 + 1] = v.y * QK_SCALE;
                qf[t * 4 + 2] = v.z * QK_SCALE; qf[t * 4 + 3] = v.w * QK_SCALE;
            }
#pragma unroll
            for (int k = 0; k < 8; k++)
                qh[k] = __floats2half2_rn(qf[2 * k], qf[2 * k + 1]);
        }

        float bshift = 0.f;
        {
            const float* k0 = sk + h * 20;
#pragma unroll
            for (int t = 0; t < 4; t++) {
                float4 kv = *(const float4*)(k0 + 4 * t);
                bshift += qf[4 * t + 0] * kv.x + qf[4 * t + 1] * kv.y +
                          qf[4 * t + 2] * kv.z + qf[4 * t + 3] * kv.w;
            }
        }

        float ssum = 0.f;
        float of[16];
#pragma unroll
        for (int e = 0; e < 16; e++) of[e] = 0.f;

        for (int j = 0; j < KWIN; ++j) {
            const uint2 pk = sidx2[i * 32 + j];
            const int r0 = (int)(pk.x & 255) << 8;
            const int r1 = (int)(40 + ((pk.x >> 8) & 255)) << 8;
            const int r2 = (int)(80 + ((pk.x >> 16) & 255)) << 8;
            const int r3 = (int)(pk.x >> 24) << 8;
            const int r4 = (int)(32 + (pk.y & 255)) << 8;
            const int r5 = (int)(64 + ((pk.y >> 8) & 255)) << 8;

            const float* kj = sk + j * 320 + h * 20;
            float facc = 0.f;
#pragma unroll
            for (int t = 0; t < 4; t++) {
                float4 kv = *(const float4*)(kj + 4 * t);
                facc += qf[4 * t + 0] * kv.x + qf[4 * t + 1] * kv.y +
                        qf[4 * t + 2] * kv.z + qf[4 * t + 3] * kv.w;
            }

            const __half* khp = skh + j * 256 + hb;
#pragma unroll
            for (int c = 0; c < 2; c++) {
                const int co = c << 7;
                H8 a0 = ldt(tKX + r0 + co), a1 = ldt(tKX + r1 + co),
                   a2 = ldt(tKX + r2 + co), a3 = ldt(tKR + r3 + co),
                   a4 = ldt(tKR + r4 + co), a5 = ldt(tKR + r5 + co);
                H8 b0 = ldt(tQX + r0 + co), b1 = ldt(tQX + r1 + co),
                   b2 = ldt(tQX + r2 + co), b3 = ldt(tQR + r3 + co),
                   b4 = ldt(tQR + r4 + co), b5 = ldt(tQR + r5 + co);
                H8 kk = ldt(khp + 8 * c);
                __half2 hq = __float2half2_rn(0.f);
                __half2 hk = hq;
#pragma unroll
                for (int l = 0; l < 4; l++) {
                    __half2 qs = sum6(a0, a1, a2, a3, a4, a5, l);
                    __half2 ks = sum6(b0, b1, b2, b3, b4, b5, l);
                    hq = __hfma2(qh[c * 4 + l], qs, hq);
                    hk = __hfma2(lane(kk, l), ks, hk);
                }
                float2 f = __half22float2(__hadd2(hq, hk));
                facc += f.x + f.y;
            }

            const float a = __expf(facc - bshift);
            ssum += a;

            const float* vj = sv + j * 320 + h * 20;
#pragma unroll
            for (int c = 0; c < 2; c++) {
                const int co = c << 7;
                H8 v0 = ldt(tVX + r0 + co), v1 = ldt(tVX + r1 + co),
                   v2 = ldt(tVX + r2 + co), v3 = ldt(tVR + r3 + co),
                   v4 = ldt(tVR + r4 + co), v5 = ldt(tVR + r5 + co);
                float4 va = *(const float4*)(vj + 8 * c);
                float4 vb = *(const float4*)(vj + 8 * c + 4);
                float2 t0 = __half22float2(sum6(v0, v1, v2, v3, v4, v5, 0));
                float2 t1 = __half22float2(sum6(v0, v1, v2, v3, v4, v5, 1));
                float2 t2 = __half22float2(sum6(v0, v1, v2, v3, v4, v5, 2));
                float2 t3 = __half22float2(sum6(v0, v1, v2, v3, v4, v5, 3));
                float* o = of + c * 8;
                o[0] += a * (va.x + t0.x); o[1] += a * (va.y + t0.y);
                o[2] += a * (va.z + t1.x); o[3] += a * (va.w + t1.y);
                o[4] += a * (vb.x + t2.x); o[5] += a * (vb.y + t2.y);
                o[6] += a * (vb.z + t3.x); o[7] += a * (vb.w + t3.y);
            }
        }

        const float inv = 1.0f / ssum;
        float4* op = (float4*)(g_mid + (size_t)pt * CDIM + hb);
#pragma unroll
        for (int t = 0; t < 4; t++)
            op[t] = make_float4(of[4 * t] * inv, of[4 * t + 1] * inv,
                                of[4 * t + 2] * inv, of[4 * t + 3] * inv);
    }
}

// ---------------------------------------------------------------------------
extern "C" void kernel_launch(void* const* d_in, const int* in_sizes, int n_in,
                              void* d_out, int out_size)
{
    const float* feats    = (const float*)d_in[0];
    const float* n_coords = (const float*)d_in[1];
    const int*   n2n      = (const int*)d_in[2];
    const float* q_xyz    = (const float*)d_in[3];
    const float* k_xyz    = (const float*)d_in[4];
    const float* v_xyz    = (const float*)d_in[5];
    const float* q_rgb    = (const float*)d_in[6];
    const float* k_rgb    = (const float*)d_in[7];
    const float* v_rgb    = (const float*)d_in[8];
    const float* qkv_w    = (const float*)d_in[9];
    const float* qkv_b    = (const float*)d_in[10];
    const float* proj_w   = (const float*)d_in[11];
    const float* proj_b   = (const float*)d_in[12];
    float* out = (float*)d_out;

    float *qkv_p = nullptr, *mid_p = nullptr;
    cudaGetSymbolAddress((void**)&qkv_p, g_qkv);
    cudaGetSymbolAddress((void**)&mid_p, g_mid);

    cudaFuncSetAttribute(win_attn, cudaFuncAttributeMaxDynamicSharedMemorySize,
                         ATTN_SMEM_BYTES);

    // 0) convert tables to fp16 (transposed rows)
    cvt_tabs<<<120, 256>>>(k_xyz, q_xyz, v_xyz, k_rgb, q_rgb, v_rgb);

    // 1) QKV projection: [65536,256] x [768,256]^T  (tf32 tensor cores)
    dim3 g1(768 / 128, NPTS / 128);
    gemm_tf32<<<g1, 256>>>(feats, qkv_w, qkv_b, qkv_p, NPTS, 768, CDIM);

    // 2) windowed attention (fused)
    win_attn<<<NWIN, 256, ATTN_SMEM_BYTES>>>(n_coords, n2n);

    // 3) output projection: [65536,256] x [256,256]^T  (tf32 tensor cores)
    dim3 g2(CDIM / 128, NPTS / 128);
    gemm_tf32<<<g2, 256>>>(mid_p, proj_w, proj_b, out, NPTS, CDIM, CDIM);
}